// round 16
// baseline (speedup 1.0000x reference)
#include <cuda_runtime.h>
#include <math.h>

#define NB 4
#define KV 1024
#define HCc 50
#define WCc 100
#define NCELL 5000
#define DIN 235
#define FEAT 256
#define NPAD 8192
#define CPL 1025
#define CPLSZ 1050625
#define CSTR 1028   /* padded fp32 row stride (float4 aligned) */

#define NORM_C   (-7.62461899f)   /* -log(2048) */
#define LOGLAST  (-0.69314718f)   /* log(1024)-log(2048) */

// ------------------------- scratch (device globals) -------------------------
__device__ float g_snms[NB * NCELL];
__device__ int   g_idx [NB * KV];
__device__ float g_vals[NB * KV];
__device__ float g_mask[NB * KV];
__device__ float g_embT[NB * DIN * KV];
__device__ float g_qkv [NB * 3 * FEAT * KV];          // fused Q|K|V
__device__ float g_msg [NB * FEAT * KV];
__device__ float g_msgp[4][NB * FEAT * KV];           // k-split partials (16 MB)
__device__ float g_cat [NB * 2 * FEAT * KV];          // rows 0-255 = x, 256-511 = msg-proj
__device__ float g_y   [NB * 2 * FEAT * KV];
__device__ float g_md  [NB * FEAT * KV];
__device__ float g_att [(size_t)NB * 4 * KV * KV];    // 67 MB
__device__ float g_coup[NB * CPLSZ];                  // 16.8 MB
__device__ float g_u   [NB * CPL];
__device__ float g_vv  [NB * CPL];
__device__ __align__(16) float g_Er [(size_t)NB * CPL * CSTR];
__device__ __align__(16) float g_EcT[(size_t)NB * CPL * CSTR];
__device__ float g_rmax[NB * CPL];
__device__ float g_cmax[NB * CPL];
__device__ __align__(16) float g_w [NB * CSTR];
__device__ __align__(16) float g_wu[NB * CSTR];

// ------------------------- NMS (simple_nms, radius 2, 2 rounds) -------------------------
__device__ __forceinline__ void maxpool5(const float* in, float* out, int tid, int nt) {
    for (int i = tid; i < NCELL; i += nt) {
        int y = i / WCc, x = i - y * WCc;
        int y0 = max(y - 2, 0), y1 = min(y + 2, HCc - 1);
        int x0 = max(x - 2, 0), x1 = min(x + 2, WCc - 1);
        float mx = -1e30f;
        for (int yy = y0; yy <= y1; yy++) {
            const float* rp = in + yy * WCc;
            for (int xx = x0; xx <= x1; xx++) mx = fmaxf(mx, rp[xx]);
        }
        out[i] = mx;
    }
}

__global__ void nms_kernel(const float* __restrict__ scores) {
    extern __shared__ float sm[];
    float* s  = sm;
    float* m  = sm + NCELL;
    float* p  = sm + 2 * NCELL;
    float* ss = sm + 3 * NCELL;
    float* q  = sm + 4 * NCELL;
    int b = blockIdx.x, tid = threadIdx.x, nt = blockDim.x;
    const float* sb = scores + b * NCELL;
    for (int i = tid; i < NCELL; i += nt) s[i] = sb[i];
    __syncthreads();
    maxpool5(s, p, tid, nt);
    __syncthreads();
    for (int i = tid; i < NCELL; i += nt) m[i] = (s[i] == p[i]) ? 1.f : 0.f;
    __syncthreads();
    for (int it = 0; it < 2; it++) {
        maxpool5(m, p, tid, nt);
        __syncthreads();
        for (int i = tid; i < NCELL; i += nt) ss[i] = (p[i] > 0.f) ? 0.f : s[i];
        __syncthreads();
        maxpool5(ss, q, tid, nt);
        __syncthreads();
        for (int i = tid; i < NCELL; i += nt) {
            bool supp = p[i] > 0.f;
            bool nm = (ss[i] == q[i]) && !supp;
            m[i] = (m[i] > 0.f || nm) ? 1.f : 0.f;
        }
        __syncthreads();
    }
    for (int i = tid; i < NCELL; i += nt)
        g_snms[b * NCELL + i] = (m[i] > 0.f) ? s[i] : 0.f;
}

// ------------------------- stable top-k via bitonic sort -------------------------
__global__ void topk_kernel() {
    extern __shared__ unsigned long long keys[];
    int b = blockIdx.x, tid = threadIdx.x, nt = blockDim.x;
    for (int i = tid; i < NPAD; i += nt) {
        unsigned long long kk = 0ull;
        if (i < NCELL) {
            float v = g_snms[b * NCELL + i];
            kk = ((unsigned long long)__float_as_uint(v) << 32) |
                 (unsigned long long)(0xFFFFFFFFu - (unsigned)i);
        }
        keys[i] = kk;
    }
    __syncthreads();
    for (int size = 2; size <= NPAD; size <<= 1) {
        for (int stride = size >> 1; stride > 0; stride >>= 1) {
            for (int i = tid; i < NPAD; i += nt) {
                int j = i ^ stride;
                if (j > i) {
                    bool asc = (i & size) != 0;
                    unsigned long long a = keys[i], c = keys[j];
                    bool sw = asc ? (a > c) : (a < c);
                    if (sw) { keys[i] = c; keys[j] = a; }
                }
            }
            __syncthreads();
        }
    }
    for (int t = tid; t < KV; t += nt) {
        unsigned long long kk = keys[t];
        float v = __uint_as_float((unsigned)(kk >> 32));
        int id = (int)(0xFFFFFFFFu - (unsigned)(kk & 0xFFFFFFFFull));
        g_idx [b * KV + t] = id;
        g_vals[b * KV + t] = v;
        g_mask[b * KV + t] = (v > 0.015f) ? 1.f : 0.f;
    }
}

// ------------------------- embedding (transposed [b][235][1024]) -------------------------
__global__ void emb_kernel(const float* __restrict__ distance) {
    int n = blockIdx.x, b = blockIdx.y, t = threadIdx.x;
    if (t >= DIN) return;
    int id = g_idx[b * KV + n];
    int vy = id / WCc, vx = id - vy * WCc;
    float out;
    if (t < 43) {
        float nvx = ((float)vx - 50.f + 0.5f) * 0.01f;
        float nvy = ((float)vy - 25.f + 0.5f) * 0.02f;
        if (t == 0) out = nvx;
        else if (t == 1) out = nvy;
        else if (t == 42) out = g_vals[b * KV + n];
        else {
            int f = (t - 2) >> 2, c = (t - 2) & 3;
            float ang = ((c & 1) ? nvy : nvx) * (float)(1 << f);
            out = (c < 2) ? sinf(ang) : cosf(ang);
        }
    } else {
        int j = t - 43;
        int c = j >> 6, rem = j & 63, sy = rem >> 3, sx = rem & 7;
        out = distance[(((size_t)b * 3 + c) * 400 + vy * 8 + sy) * 800 + vx * 8 + sx];
    }
    g_embT[((size_t)b * DIN + t) * KV + n] = out;
}

// ===== weight GEMM (R11 proven): 64x64x16 tile, 256 threads, 4x4/thread, double-buffered =====
template<int EPI>
__global__ void __launch_bounds__(256) gemm_k(
        const float* __restrict__ A, const float* __restrict__ B,
        float* __restrict__ C, const float* __restrict__ bias,
        const float* __restrict__ bn, int M, int K, long sB, long sC) {
    int b = blockIdx.z;
    const float* Bb = B + (size_t)b * sB;
    float* Cb = C + (size_t)b * sC;
    int m0 = blockIdx.y * 64, n0 = blockIdx.x * 64;
    __shared__ float As[2][16][68];
    __shared__ float Bs[2][16][68];
    int tid = threadIdx.x;
    int tx = tid & 15, ty = tid >> 4;
    int ac = tid & 15, ar = tid >> 4;
    int bnn = tid & 63, bk = tid >> 6;

    float ra[4], rb[4];
#pragma unroll
    for (int p = 0; p < 4; p++)
        As[0][ac][ar + p * 16] = (ac < K) ? A[(size_t)(m0 + ar + p * 16) * K + ac] : 0.f;
#pragma unroll
    for (int p = 0; p < 4; p++) {
        int k = bk + p * 4;
        Bs[0][k][bnn] = (k < K) ? Bb[(size_t)k * KV + n0 + bnn] : 0.f;
    }
    __syncthreads();

    float acc[4][4] = {};
    int ntiles = (K + 15) >> 4;
    for (int t = 0; t < ntiles; t++) {
        int k0n = (t + 1) << 4;
        if (t + 1 < ntiles) {
            int ka = k0n + ac;
#pragma unroll
            for (int p = 0; p < 4; p++)
                ra[p] = (ka < K) ? A[(size_t)(m0 + ar + p * 16) * K + ka] : 0.f;
#pragma unroll
            for (int p = 0; p < 4; p++) {
                int k = k0n + bk + p * 4;
                rb[p] = (k < K) ? Bb[(size_t)k * KV + n0 + bnn] : 0.f;
            }
        }
        int cur = t & 1;
#pragma unroll
        for (int kk = 0; kk < 16; kk++) {
            float4 a0 = *(const float4*)&As[cur][kk][ty * 4];
            float4 b0 = *(const float4*)&Bs[cur][kk][tx * 4];
            float av[4] = {a0.x, a0.y, a0.z, a0.w};
            float bv[4] = {b0.x, b0.y, b0.z, b0.w};
#pragma unroll
            for (int i = 0; i < 4; i++)
#pragma unroll
                for (int j = 0; j < 4; j++) acc[i][j] += av[i] * bv[j];
        }
        if (t + 1 < ntiles) {
            int nxt = cur ^ 1;
#pragma unroll
            for (int p = 0; p < 4; p++) As[nxt][ac][ar + p * 16] = ra[p];
#pragma unroll
            for (int p = 0; p < 4; p++) Bs[nxt][bk + p * 4][bnn] = rb[p];
        }
        __syncthreads();
    }
#pragma unroll
    for (int i = 0; i < 4; i++) {
        int m = m0 + ty * 4 + i;
        float bi = bias[m];
        float g = 1.f, bt = 0.f, mu = 0.f, iv = 1.f;
        if (EPI == 1) {
            g = bn[m]; bt = bn[M + m]; mu = bn[2 * M + m];
            iv = rsqrtf(bn[3 * M + m] + 1e-5f);
        }
        float* cp = &Cb[(size_t)m * KV + n0 + tx * 4];
        float4 old;
        if (EPI == 2) old = *(const float4*)cp;
        float ov[4];
#pragma unroll
        for (int j = 0; j < 4; j++) {
            float v = acc[i][j] + bi;
            if (EPI == 1) { v = g * (v - mu) * iv + bt; v = fmaxf(v, 0.f); }
            ov[j] = v;
        }
        if (EPI == 2) { ov[0] += old.x; ov[1] += old.y; ov[2] += old.z; ov[3] += old.w; }
        float4 o = make_float4(ov[0], ov[1], ov[2], ov[3]);
        *(float4*)cp = o;
    }
}

// ------------- attention score: att[bh][n][m] = Qh^T Kh / 8
//               128x128 tile, 256 threads, 8x8/thread, double-buffered -------------
__global__ void __launch_bounds__(256) attn_score_k() {
    int bh = blockIdx.z, b = bh >> 2, h = bh & 3;
    const float* qh = g_qkv + (size_t)b * 3 * FEAT * KV + (size_t)h * KV;
    const float* kh = qh + (size_t)FEAT * KV;
    float* ah = g_att + (size_t)bh * KV * KV;
    int n0 = blockIdx.y * 128, m0 = blockIdx.x * 128;
    __shared__ float Qs[2][16][132];
    __shared__ float Ks[2][16][132];
    int tid = threadIdx.x, tx = tid & 15, ty = tid >> 4;
    int nn = tid & 127, kr = tid >> 7;           // kr 0..1, 8 k's per thread
    const float* Qp = qh + n0 + nn;
    const float* Kp = kh + m0 + nn;

    float ra[8], rb[8];
#pragma unroll
    for (int p = 0; p < 8; p++) {
        int k = kr + p * 2;
        Qs[0][k][nn] = Qp[(size_t)k * 4 * KV];
        Ks[0][k][nn] = Kp[(size_t)k * 4 * KV];
    }
    __syncthreads();
    float acc[8][8] = {};
#pragma unroll
    for (int t = 0; t < 4; t++) {
        if (t < 3) {
#pragma unroll
            for (int p = 0; p < 8; p++) {
                int k = ((t + 1) << 4) + kr + p * 2;
                ra[p] = Qp[(size_t)k * 4 * KV];
                rb[p] = Kp[(size_t)k * 4 * KV];
            }
        }
        int cur = t & 1;
#pragma unroll
        for (int kk = 0; kk < 16; kk++) {
            float4 a0 = *(const float4*)&Qs[cur][kk][ty * 8];
            float4 a1 = *(const float4*)&Qs[cur][kk][ty * 8 + 4];
            float4 b0 = *(const float4*)&Ks[cur][kk][tx * 8];
            float4 b1 = *(const float4*)&Ks[cur][kk][tx * 8 + 4];
            float av[8] = {a0.x, a0.y, a0.z, a0.w, a1.x, a1.y, a1.z, a1.w};
            float bv[8] = {b0.x, b0.y, b0.z, b0.w, b1.x, b1.y, b1.z, b1.w};
#pragma unroll
            for (int i = 0; i < 8; i++)
#pragma unroll
                for (int j = 0; j < 8; j++) acc[i][j] += av[i] * bv[j];
        }
        if (t < 3) {
            int nxt = cur ^ 1;
#pragma unroll
            for (int p = 0; p < 8; p++) {
                Qs[nxt][kr + p * 2][nn] = ra[p];
                Ks[nxt][kr + p * 2][nn] = rb[p];
            }
        }
        __syncthreads();
    }
#pragma unroll
    for (int i = 0; i < 8; i++) {
        float* op = &ah[(size_t)(n0 + ty * 8 + i) * KV + m0 + tx * 8];
        float4 o0 = make_float4(acc[i][0] * 0.125f, acc[i][1] * 0.125f,
                                acc[i][2] * 0.125f, acc[i][3] * 0.125f);
        float4 o1 = make_float4(acc[i][4] * 0.125f, acc[i][5] * 0.125f,
                                acc[i][6] * 0.125f, acc[i][7] * 0.125f);
        *(float4*)op = o0;
        *(float4*)(op + 4) = o1;
    }
}

// ------------------------- mask + softmax over rows of g_att (R11) -------------------------
__global__ void softmax_k() {
    int bh = blockIdx.y, b = bh >> 2, n = blockIdx.x;
    float* row = g_att + (size_t)bh * KV * KV + (size_t)n * KV;
    const float* mk = g_mask + b * KV;
    int tid = threadIdx.x;
    float mrow = mk[n];
    float x[4]; float mx = -1e30f;
#pragma unroll
    for (int i = 0; i < 4; i++) {
        int m = tid + (i << 8);
        float v = row[m];
        if (mrow * mk[m] == 0.f) v = -1e9f;
        x[i] = v; mx = fmaxf(mx, v);
    }
    __shared__ float red[8];
    for (int o = 16; o; o >>= 1) mx = fmaxf(mx, __shfl_xor_sync(0xffffffffu, mx, o));
    if ((tid & 31) == 0) red[tid >> 5] = mx;
    __syncthreads();
    float bm = red[0];
#pragma unroll
    for (int w = 1; w < 8; w++) bm = fmaxf(bm, red[w]);
    __syncthreads();
    float s = 0.f;
#pragma unroll
    for (int i = 0; i < 4; i++) { x[i] = __expf(x[i] - bm); s += x[i]; }
    for (int o = 16; o; o >>= 1) s += __shfl_xor_sync(0xffffffffu, s, o);
    if ((tid & 31) == 0) red[tid >> 5] = s;
    __syncthreads();
    float bs = 0.f;
#pragma unroll
    for (int w = 0; w < 8; w++) bs += red[w];
    float inv = 1.f / bs;
#pragma unroll
    for (int i = 0; i < 4; i++) row[tid + (i << 8)] = x[i] * inv;
}

// ------- attention apply, K-SPLIT x4 (R15 proven) -------
__global__ void __launch_bounds__(256) attn_apply_k() {
    int bh = blockIdx.z, b = bh >> 2, h = bh & 3;
    int kc = blockIdx.y;
    const float* ph = g_att + (size_t)bh * KV * KV;
    const float* vh = g_qkv + (size_t)b * 3 * FEAT * KV + (size_t)2 * FEAT * KV
                    + (size_t)h * KV;
    float* outp = g_msgp[kc] + (size_t)b * FEAT * KV;
    int n0 = blockIdx.x * 64;
    int mbase = kc * 256;
    __shared__ float As[2][16][68];
    __shared__ float Bs[2][16][68];
    int tid = threadIdx.x, tx = tid & 15, ty = tid >> 4;
    int ac = tid & 15, ar = tid >> 4;
    int bc = tid & 15, br = tid >> 4;

    float ra[4], rb[4];
#pragma unroll
    for (int p = 0; p < 4; p++) {
        int d = ar + p * 16;
        As[0][ac][d] = vh[(size_t)(d * 4) * KV + mbase + ac];
        int n = br + p * 16;
        Bs[0][bc][n] = ph[(size_t)(n0 + n) * KV + mbase + bc];
    }
    __syncthreads();
    float acc[4][4] = {};
    for (int t = 0; t < 16; t++) {
        int m0n = mbase + ((t + 1) << 4);
        if (t < 15) {
#pragma unroll
            for (int p = 0; p < 4; p++) {
                int d = ar + p * 16;
                ra[p] = vh[(size_t)(d * 4) * KV + m0n + ac];
                int n = br + p * 16;
                rb[p] = ph[(size_t)(n0 + n) * KV + m0n + bc];
            }
        }
        int cur = t & 1;
#pragma unroll
        for (int kk = 0; kk < 16; kk++) {
            float4 a0 = *(const float4*)&As[cur][kk][ty * 4];
            float4 b0 = *(const float4*)&Bs[cur][kk][tx * 4];
            float av[4] = {a0.x, a0.y, a0.z, a0.w};
            float bv[4] = {b0.x, b0.y, b0.z, b0.w};
#pragma unroll
            for (int i = 0; i < 4; i++)
#pragma unroll
                for (int j = 0; j < 4; j++) acc[i][j] += av[i] * bv[j];
        }
        if (t < 15) {
            int nxt = cur ^ 1;
#pragma unroll
            for (int p = 0; p < 4; p++) {
                As[nxt][ac][ar + p * 16] = ra[p];
                Bs[nxt][bc][br + p * 16] = rb[p];
            }
        }
        __syncthreads();
    }
#pragma unroll
    for (int i = 0; i < 4; i++) {
        int d = ty * 4 + i;
        float4 o = make_float4(acc[i][0], acc[i][1], acc[i][2], acc[i][3]);
        *(float4*)&outp[(size_t)(d * 4 + h) * KV + n0 + tx * 4] = o;
    }
}

// ------------------------- reduce 4 k-split partials into g_msg -------------------------
__global__ void msg_reduce_k() {
    const size_t N = (size_t)NB * FEAT * KV / 4;
    size_t i = (size_t)blockIdx.x * 256 + threadIdx.x;
    if (i >= N) return;
    const float4* p0 = reinterpret_cast<const float4*>(g_msgp[0]);
    const float4* p1 = reinterpret_cast<const float4*>(g_msgp[1]);
    const float4* p2 = reinterpret_cast<const float4*>(g_msgp[2]);
    const float4* p3 = reinterpret_cast<const float4*>(g_msgp[3]);
    float4 a = p0[i], b = p1[i], c = p2[i], d = p3[i];
    float4 o = make_float4(a.x + b.x + c.x + d.x, a.y + b.y + c.y + d.y,
                           a.z + b.z + c.z + d.z, a.w + b.w + c.w + d.w);
    reinterpret_cast<float4*>(g_msg)[i] = o;
}

// ------------------------- Gram: coup[n][m] = md^T md / 16
//               128x128 tile, 256 threads, 8x8/thread, double-buffered -------------------------
__global__ void __launch_bounds__(256) gram_k() {
    int b = blockIdx.z;
    const float* mb = g_md + (size_t)b * FEAT * KV;
    float* cb = g_coup + (size_t)b * CPLSZ;
    int n0 = blockIdx.y * 128, m0 = blockIdx.x * 128;
    __shared__ float Ns[2][16][132];
    __shared__ float Ms[2][16][132];
    int tid = threadIdx.x, tx = tid & 15, ty = tid >> 4;
    int nn = tid & 127, kr = tid >> 7;
    const float* Np = mb + n0 + nn;
    const float* Mp = mb + m0 + nn;

    float ra[8], rb[8];
#pragma unroll
    for (int p = 0; p < 8; p++) {
        int k = kr + p * 2;
        Ns[0][k][nn] = Np[(size_t)k * KV];
        Ms[0][k][nn] = Mp[(size_t)k * KV];
    }
    __syncthreads();
    float acc[8][8] = {};
    for (int t = 0; t < 16; t++) {
        if (t < 15) {
            int k0n = (t + 1) << 4;
#pragma unroll
            for (int p = 0; p < 8; p++) {
                int k = k0n + kr + p * 2;
                ra[p] = Np[(size_t)k * KV];
                rb[p] = Mp[(size_t)k * KV];
            }
        }
        int cur = t & 1;
#pragma unroll
        for (int kk = 0; kk < 16; kk++) {
            float4 a0 = *(const float4*)&Ns[cur][kk][ty * 8];
            float4 a1 = *(const float4*)&Ns[cur][kk][ty * 8 + 4];
            float4 b0 = *(const float4*)&Ms[cur][kk][tx * 8];
            float4 b1 = *(const float4*)&Ms[cur][kk][tx * 8 + 4];
            float av[8] = {a0.x, a0.y, a0.z, a0.w, a1.x, a1.y, a1.z, a1.w};
            float bv[8] = {b0.x, b0.y, b0.z, b0.w, b1.x, b1.y, b1.z, b1.w};
#pragma unroll
            for (int i = 0; i < 8; i++)
#pragma unroll
                for (int j = 0; j < 8; j++) acc[i][j] += av[i] * bv[j];
        }
        if (t < 15) {
            int nxt = cur ^ 1;
#pragma unroll
            for (int p = 0; p < 8; p++) {
                Ns[nxt][kr + p * 2][nn] = ra[p];
                Ms[nxt][kr + p * 2][nn] = rb[p];
            }
        }
        __syncthreads();
    }
    const float sc = 1.f / 16.f;
#pragma unroll
    for (int i = 0; i < 8; i++) {
        float* op = &cb[(size_t)(n0 + ty * 8 + i) * CPL + m0 + tx * 8];
#pragma unroll
        for (int j = 0; j < 8; j++) op[j] = acc[i][j] * sc;
    }
}

__global__ void border_k(const float* __restrict__ alpha) {
    float a = alpha[0];
    int b = blockIdx.y;
    int i = blockIdx.x * 256 + threadIdx.x;
    float* cb = g_coup + (size_t)b * CPLSZ;
    if (i < CPL) {
        cb[(size_t)i * CPL + 1024] = a;
        cb[(size_t)1024 * CPL + i] = a;
    }
}

// ------------------------- Sinkhorn precompute (fp32) -------------------------
__global__ void rowmax_k() {
    int b = blockIdx.y;
    int n = blockIdx.x * 8 + (threadIdx.x >> 5);
    int lane = threadIdx.x & 31;
    if (n >= CPL) return;
    const float* row = g_coup + (size_t)b * CPLSZ + (size_t)n * CPL;
    float m = -1e30f;
    for (int j = lane; j < CPL; j += 32) m = fmaxf(m, row[j]);
    for (int o = 16; o; o >>= 1) m = fmaxf(m, __shfl_xor_sync(0xffffffffu, m, o));
    if (!lane) g_rmax[b * CPL + n] = m;
}

__global__ void colmax_k() {
    int b = blockIdx.y;
    int lane = threadIdx.x & 31, r = threadIdx.x >> 5;
    int col = blockIdx.x * 32 + lane;
    const float* cp = g_coup + (size_t)b * CPLSZ;
    float m = -1e30f;
    if (col < CPL)
        for (int n = r; n < CPL; n += 8) m = fmaxf(m, cp[(size_t)n * CPL + col]);
    __shared__ float sm[8][33];
    sm[r][lane] = m;
    __syncthreads();
    if (r == 0 && col < CPL) {
        float M = sm[0][lane];
        for (int w = 1; w < 8; w++) M = fmaxf(M, sm[w][lane]);
        g_cmax[b * CPL + col] = M;
    }
}

__global__ void build_exp_k() {
    int b = blockIdx.z;
    int j0 = blockIdx.x * 32, n0 = blockIdx.y * 32;
    const float* cp = g_coup + (size_t)b * CPLSZ;
    __shared__ float t[32][33];
    int tx = threadIdx.x;
    for (int r = threadIdx.y; r < 32; r += 8) {
        int n = n0 + r, j = j0 + tx;
        float c = (n < CPL && j < CPL) ? cp[(size_t)n * CPL + j] : -1e30f;
        if (n < CPL && j < CSTR) {
            float rm = g_rmax[b * CPL + n];
            g_Er[((size_t)b * CPL + n) * CSTR + j] = (j < CPL) ? __expf(c - rm) : 0.f;
        }
        float cm = (j < CPL) ? g_cmax[b * CPL + j] : 0.f;
        t[tx][r] = (n < CPL && j < CPL) ? __expf(c - cm) : 0.f;
    }
    __syncthreads();
    for (int r = threadIdx.y; r < 32; r += 8) {
        int j = j0 + r, n = n0 + tx;
        if (j < CPL && n < CSTR)
            g_EcT[((size_t)b * CPL + j) * CSTR + n] = t[r][tx];
    }
}

__global__ void init_w_k() {
    int i = blockIdx.x * 256 + threadIdx.x;
    if (i < NB * CSTR) {
        int j = i % CSTR;
        g_w[i]  = (j < CPL) ? 1.f : 0.f;
        g_wu[i] = 0.f;
    }
}

// ------------------------- Sinkhorn GEMV passes (fp32, multi-launch) -------------------------
__global__ void sink_row_f() {
    int b = blockIdx.y;
    int n = blockIdx.x * 8 + (threadIdx.x >> 5);
    int lane = threadIdx.x & 31;
    if (n >= CPL) return;
    const float4* row = reinterpret_cast<const float4*>(g_Er + ((size_t)b * CPL + n) * CSTR);
    const float4* w4  = reinterpret_cast<const float4*>(g_w + b * CSTR);
    float dot = 0.f;
#pragma unroll 4
    for (int i = lane; i < CSTR / 4; i += 32) {
        float4 e = row[i], ww = w4[i];
        dot += e.x * ww.x; dot += e.y * ww.y; dot += e.z * ww.z; dot += e.w * ww.w;
    }
    for (int o = 16; o; o >>= 1) dot += __shfl_xor_sync(0xffffffffu, dot, o);
    if (!lane) {
        float lmu = (n < 1024) ? NORM_C : LOGLAST;
        float u = lmu - g_rmax[b * CPL + n] - logf(dot);
        g_u[b * CPL + n] = u;
        g_wu[b * CSTR + n] = expf(u);
    }
}

__global__ void sink_col_f() {
    int b = blockIdx.y;
    int j = blockIdx.x * 8 + (threadIdx.x >> 5);
    int lane = threadIdx.x & 31;
    if (j >= CPL) return;
    const float4* row = reinterpret_cast<const float4*>(g_EcT + ((size_t)b * CPL + j) * CSTR);
    const float4* w4  = reinterpret_cast<const float4*>(g_wu + b * CSTR);
    float dot = 0.f;
#pragma unroll 4
    for (int i = lane; i < CSTR / 4; i += 32) {
        float4 e = row[i], ww = w4[i];
        dot += e.x * ww.x; dot += e.y * ww.y; dot += e.z * ww.z; dot += e.w * ww.w;
    }
    for (int o = 16; o; o >>= 1) dot += __shfl_xor_sync(0xffffffffu, dot, o);
    if (!lane) {
        float lnu = (j < 1024) ? NORM_C : LOGLAST;
        float v = lnu - g_cmax[b * CPL + j] - logf(dot);
        g_vv[b * CPL + j] = v;
        g_w[b * CSTR + j] = expf(v);
    }
}

__global__ void out_k(float* __restrict__ out) {
    int b = blockIdx.y, n = blockIdx.x;
    const float* cb = g_coup + (size_t)b * CPLSZ + (size_t)n * CPL;
    float un = g_u[b * CPL + n];
    const float* v = g_vv + b * CPL;
    float* ob = out + (size_t)b * CPLSZ + (size_t)n * CPL;
    for (int j = threadIdx.x; j < CPL; j += 256)
        ob[j] = cb[j] + un + v[j] - NORM_C;
}

// ------------------------- host -------------------------
static inline void gemm(const float* A, const float* B, float* C, const float* bias,
                        int M, int K, long sB, long sC, int epi, const float* bn) {
    dim3 g(16, M / 64, NB);
    if (epi == 0)      gemm_k<0><<<g, 256>>>(A, B, C, bias, bn, M, K, sB, sC);
    else if (epi == 1) gemm_k<1><<<g, 256>>>(A, B, C, bias, bn, M, K, sB, sC);
    else               gemm_k<2><<<g, 256>>>(A, B, C, bias, bn, M, K, sB, sC);
}

extern "C" void kernel_launch(void* const* d_in, const int* in_sizes, int n_in,
                              void* d_out, int out_size) {
    const float* scores   = (const float*)d_in[0];
    const float* distance = (const float*)d_in[1];
    const float* enc_W0   = (const float*)d_in[2];
    const float* enc_b0   = (const float*)d_in[3];
    const float* enc_bn   = (const float*)d_in[4];
    const float* enc_W1   = (const float*)d_in[5];
    const float* enc_b1   = (const float*)d_in[6];
    const float* gnn_Wqkv = (const float*)d_in[7];
    const float* gnn_bqkv = (const float*)d_in[8];
    const float* gnn_Wm   = (const float*)d_in[9];
    const float* gnn_bm   = (const float*)d_in[10];
    const float* gnn_W1   = (const float*)d_in[11];
    const float* gnn_b1   = (const float*)d_in[12];
    const float* gnn_bn   = (const float*)d_in[13];
    const float* gnn_W2   = (const float*)d_in[14];
    const float* gnn_b2   = (const float*)d_in[15];
    const float* final_W  = (const float*)d_in[16];
    const float* final_b  = (const float*)d_in[17];
    const float* alpha    = (const float*)d_in[18];
    float* out = (float*)d_out;

    static bool attr_done = false;
    if (!attr_done) {
        cudaFuncSetAttribute(nms_kernel,  cudaFuncAttributeMaxDynamicSharedMemorySize, 5 * NCELL * 4);
        cudaFuncSetAttribute(topk_kernel, cudaFuncAttributeMaxDynamicSharedMemorySize, NPAD * 8);
        attr_done = true;
    }

    float *devEmb=nullptr, *devQKV=nullptr, *devMsg=nullptr, *devCat=nullptr,
          *devY=nullptr, *devMd=nullptr;
    cudaGetSymbolAddress((void**)&devEmb, g_embT);
    cudaGetSymbolAddress((void**)&devQKV, g_qkv);
    cudaGetSymbolAddress((void**)&devMsg, g_msg);
    cudaGetSymbolAddress((void**)&devCat, g_cat);
    cudaGetSymbolAddress((void**)&devY,   g_y);
    cudaGetSymbolAddress((void**)&devMd,  g_md);

    const long sF  = (long)FEAT * KV;       // 262144
    const long s2F = 2L * FEAT * KV;        // 524288
    const long s3F = 3L * FEAT * KV;        // 786432
    const long sE  = (long)DIN * KV;

    // 1. NMS + top-k + embedding
    nms_kernel<<<NB, 256, 5 * NCELL * 4>>>(scores);
    topk_kernel<<<NB, 256, NPAD * 8>>>();
    emb_kernel<<<dim3(KV, NB), 256>>>(distance);

    // 2. encoder
    gemm(enc_W0, devEmb, devY, enc_b0, FEAT, DIN, sE, sF, 1, enc_bn);
    gemm(enc_W1, devY, devCat, enc_b1, FEAT, FEAT, sF, s2F, 0, nullptr);

    // 3. GNN layers
    for (int l = 0; l < 4; l++) {
        gemm(gnn_Wqkv + (size_t)l * 3 * FEAT * FEAT, devCat, devQKV,
             gnn_bqkv + l * 3 * FEAT, 3 * FEAT, FEAT, s2F, s3F, 0, nullptr);

        attn_score_k<<<dim3(8, 8, NB * 4), 256>>>();
        softmax_k<<<dim3(KV, NB * 4), 256>>>();
        attn_apply_k<<<dim3(16, 4, NB * 4), 256>>>();
        msg_reduce_k<<<4096, 256>>>();

        gemm(gnn_Wm + (size_t)l * FEAT * FEAT, devMsg, devCat + (size_t)FEAT * KV,
             gnn_bm + l * FEAT, FEAT, FEAT, sF, s2F, 0, nullptr);
        gemm(gnn_W1 + (size_t)l * 512 * 512, devCat, devY,
             gnn_b1 + l * 512, 512, 512, s2F, s2F, 1, gnn_bn + (size_t)l * 4 * 512);
        gemm(gnn_W2 + (size_t)l * FEAT * 512, devY, devCat,
             gnn_b2 + l * FEAT, FEAT, 512, s2F, s2F, 2, nullptr);
    }

    // 4. final descriptors + Gram + couplings
    gemm(final_W, devCat, devMd, final_b, FEAT, FEAT, s2F, sF, 0, nullptr);
    gram_k<<<dim3(8, 8, NB), 256>>>();
    border_k<<<dim3(5, NB), 256>>>(alpha);

    // 5. Sinkhorn: factorized fp32 exp-matrices -> GEMV passes
    rowmax_k<<<dim3(129, NB), 256>>>();
    colmax_k<<<dim3(33, NB), 256>>>();
    build_exp_k<<<dim3(33, 33, NB), dim3(32, 8)>>>();
    init_w_k<<<17, 256>>>();
    for (int it = 0; it < 100; it++) {
        sink_row_f<<<dim3(129, NB), 256>>>();
        sink_col_f<<<dim3(129, NB), 256>>>();
    }

    // 6. output
    out_k<<<dim3(CPL, NB), 256>>>(out);
}

// round 17
// speedup vs baseline: 1.0186x; 1.0186x over previous
#include <cuda_runtime.h>
#include <math.h>

#define NB 4
#define KV 1024
#define HCc 50
#define WCc 100
#define NCELL 5000
#define DIN 235
#define FEAT 256
#define NPAD 8192
#define CPL 1025
#define CPLSZ 1050625
#define CSTR 1028   /* padded fp32 row stride (float4 aligned) */

#define NORM_C   (-7.62461899f)   /* -log(2048) */
#define LOGLAST  (-0.69314718f)   /* log(1024)-log(2048) */

// ------------------------- scratch (device globals) -------------------------
__device__ float g_snms[NB * NCELL];
__device__ int   g_idx [NB * KV];
__device__ float g_vals[NB * KV];
__device__ float g_mask[NB * KV];
__device__ float g_embT[NB * DIN * KV];
__device__ float g_qkv [NB * 3 * FEAT * KV];          // fused Q|K|V
__device__ float g_msg [NB * FEAT * KV];
__device__ float g_msgp[4][NB * FEAT * KV];           // k-split partials (16 MB)
__device__ float g_cat [NB * 2 * FEAT * KV];          // rows 0-255 = x, 256-511 = msg-proj
__device__ float g_y   [NB * 2 * FEAT * KV];
__device__ float g_md  [NB * FEAT * KV];
__device__ float g_att [(size_t)NB * 4 * KV * KV];    // 67 MB
__device__ float g_coup[NB * CPLSZ];                  // 16.8 MB
__device__ float g_u   [NB * CPL];
__device__ float g_vv  [NB * CPL];
__device__ __align__(16) float g_Er [(size_t)NB * CPL * CSTR];
__device__ __align__(16) float g_EcT[(size_t)NB * CPL * CSTR];
__device__ float g_rmax[NB * CPL];
__device__ float g_cmax[NB * CPL];
__device__ __align__(16) float g_w [NB * CSTR];
__device__ __align__(16) float g_wu[NB * CSTR];

// ------------------------- NMS (simple_nms, radius 2, 2 rounds) -------------------------
__device__ __forceinline__ void maxpool5(const float* in, float* out, int tid, int nt) {
    for (int i = tid; i < NCELL; i += nt) {
        int y = i / WCc, x = i - y * WCc;
        int y0 = max(y - 2, 0), y1 = min(y + 2, HCc - 1);
        int x0 = max(x - 2, 0), x1 = min(x + 2, WCc - 1);
        float mx = -1e30f;
        for (int yy = y0; yy <= y1; yy++) {
            const float* rp = in + yy * WCc;
            for (int xx = x0; xx <= x1; xx++) mx = fmaxf(mx, rp[xx]);
        }
        out[i] = mx;
    }
}

__global__ void nms_kernel(const float* __restrict__ scores) {
    extern __shared__ float sm[];
    float* s  = sm;
    float* m  = sm + NCELL;
    float* p  = sm + 2 * NCELL;
    float* ss = sm + 3 * NCELL;
    float* q  = sm + 4 * NCELL;
    int b = blockIdx.x, tid = threadIdx.x, nt = blockDim.x;
    const float* sb = scores + b * NCELL;
    for (int i = tid; i < NCELL; i += nt) s[i] = sb[i];
    __syncthreads();
    maxpool5(s, p, tid, nt);
    __syncthreads();
    for (int i = tid; i < NCELL; i += nt) m[i] = (s[i] == p[i]) ? 1.f : 0.f;
    __syncthreads();
    for (int it = 0; it < 2; it++) {
        maxpool5(m, p, tid, nt);
        __syncthreads();
        for (int i = tid; i < NCELL; i += nt) ss[i] = (p[i] > 0.f) ? 0.f : s[i];
        __syncthreads();
        maxpool5(ss, q, tid, nt);
        __syncthreads();
        for (int i = tid; i < NCELL; i += nt) {
            bool supp = p[i] > 0.f;
            bool nm = (ss[i] == q[i]) && !supp;
            m[i] = (m[i] > 0.f || nm) ? 1.f : 0.f;
        }
        __syncthreads();
    }
    for (int i = tid; i < NCELL; i += nt)
        g_snms[b * NCELL + i] = (m[i] > 0.f) ? s[i] : 0.f;
}

// ------------------------- stable top-k via bitonic sort -------------------------
__global__ void topk_kernel() {
    extern __shared__ unsigned long long keys[];
    int b = blockIdx.x, tid = threadIdx.x, nt = blockDim.x;
    for (int i = tid; i < NPAD; i += nt) {
        unsigned long long kk = 0ull;
        if (i < NCELL) {
            float v = g_snms[b * NCELL + i];
            kk = ((unsigned long long)__float_as_uint(v) << 32) |
                 (unsigned long long)(0xFFFFFFFFu - (unsigned)i);
        }
        keys[i] = kk;
    }
    __syncthreads();
    for (int size = 2; size <= NPAD; size <<= 1) {
        for (int stride = size >> 1; stride > 0; stride >>= 1) {
            for (int i = tid; i < NPAD; i += nt) {
                int j = i ^ stride;
                if (j > i) {
                    bool asc = (i & size) != 0;
                    unsigned long long a = keys[i], c = keys[j];
                    bool sw = asc ? (a > c) : (a < c);
                    if (sw) { keys[i] = c; keys[j] = a; }
                }
            }
            __syncthreads();
        }
    }
    for (int t = tid; t < KV; t += nt) {
        unsigned long long kk = keys[t];
        float v = __uint_as_float((unsigned)(kk >> 32));
        int id = (int)(0xFFFFFFFFu - (unsigned)(kk & 0xFFFFFFFFull));
        g_idx [b * KV + t] = id;
        g_vals[b * KV + t] = v;
        g_mask[b * KV + t] = (v > 0.015f) ? 1.f : 0.f;
    }
}

// ------------------------- embedding (transposed [b][235][1024]) -------------------------
__global__ void emb_kernel(const float* __restrict__ distance) {
    int n = blockIdx.x, b = blockIdx.y, t = threadIdx.x;
    if (t >= DIN) return;
    int id = g_idx[b * KV + n];
    int vy = id / WCc, vx = id - vy * WCc;
    float out;
    if (t < 43) {
        float nvx = ((float)vx - 50.f + 0.5f) * 0.01f;
        float nvy = ((float)vy - 25.f + 0.5f) * 0.02f;
        if (t == 0) out = nvx;
        else if (t == 1) out = nvy;
        else if (t == 42) out = g_vals[b * KV + n];
        else {
            int f = (t - 2) >> 2, c = (t - 2) & 3;
            float ang = ((c & 1) ? nvy : nvx) * (float)(1 << f);
            out = (c < 2) ? sinf(ang) : cosf(ang);
        }
    } else {
        int j = t - 43;
        int c = j >> 6, rem = j & 63, sy = rem >> 3, sx = rem & 7;
        out = distance[(((size_t)b * 3 + c) * 400 + vy * 8 + sy) * 800 + vx * 8 + sx];
    }
    g_embT[((size_t)b * DIN + t) * KV + n] = out;
}

// ===== weight GEMM (R11 proven): 64x64x16 tile, 256 threads, 4x4/thread, double-buffered =====
template<int EPI>
__global__ void __launch_bounds__(256) gemm_k(
        const float* __restrict__ A, const float* __restrict__ B,
        float* __restrict__ C, const float* __restrict__ bias,
        const float* __restrict__ bn, int M, int K, long sB, long sC) {
    int b = blockIdx.z;
    const float* Bb = B + (size_t)b * sB;
    float* Cb = C + (size_t)b * sC;
    int m0 = blockIdx.y * 64, n0 = blockIdx.x * 64;
    __shared__ float As[2][16][68];
    __shared__ float Bs[2][16][68];
    int tid = threadIdx.x;
    int tx = tid & 15, ty = tid >> 4;
    int ac = tid & 15, ar = tid >> 4;
    int bnn = tid & 63, bk = tid >> 6;

    float ra[4], rb[4];
#pragma unroll
    for (int p = 0; p < 4; p++)
        As[0][ac][ar + p * 16] = (ac < K) ? A[(size_t)(m0 + ar + p * 16) * K + ac] : 0.f;
#pragma unroll
    for (int p = 0; p < 4; p++) {
        int k = bk + p * 4;
        Bs[0][k][bnn] = (k < K) ? Bb[(size_t)k * KV + n0 + bnn] : 0.f;
    }
    __syncthreads();

    float acc[4][4] = {};
    int ntiles = (K + 15) >> 4;
    for (int t = 0; t < ntiles; t++) {
        int k0n = (t + 1) << 4;
        if (t + 1 < ntiles) {
            int ka = k0n + ac;
#pragma unroll
            for (int p = 0; p < 4; p++)
                ra[p] = (ka < K) ? A[(size_t)(m0 + ar + p * 16) * K + ka] : 0.f;
#pragma unroll
            for (int p = 0; p < 4; p++) {
                int k = k0n + bk + p * 4;
                rb[p] = (k < K) ? Bb[(size_t)k * KV + n0 + bnn] : 0.f;
            }
        }
        int cur = t & 1;
#pragma unroll
        for (int kk = 0; kk < 16; kk++) {
            float4 a0 = *(const float4*)&As[cur][kk][ty * 4];
            float4 b0 = *(const float4*)&Bs[cur][kk][tx * 4];
            float av[4] = {a0.x, a0.y, a0.z, a0.w};
            float bv[4] = {b0.x, b0.y, b0.z, b0.w};
#pragma unroll
            for (int i = 0; i < 4; i++)
#pragma unroll
                for (int j = 0; j < 4; j++) acc[i][j] += av[i] * bv[j];
        }
        if (t + 1 < ntiles) {
            int nxt = cur ^ 1;
#pragma unroll
            for (int p = 0; p < 4; p++) As[nxt][ac][ar + p * 16] = ra[p];
#pragma unroll
            for (int p = 0; p < 4; p++) Bs[nxt][bk + p * 4][bnn] = rb[p];
        }
        __syncthreads();
    }
#pragma unroll
    for (int i = 0; i < 4; i++) {
        int m = m0 + ty * 4 + i;
        float bi = bias[m];
        float g = 1.f, bt = 0.f, mu = 0.f, iv = 1.f;
        if (EPI == 1) {
            g = bn[m]; bt = bn[M + m]; mu = bn[2 * M + m];
            iv = rsqrtf(bn[3 * M + m] + 1e-5f);
        }
        float* cp = &Cb[(size_t)m * KV + n0 + tx * 4];
        float4 old;
        if (EPI == 2) old = *(const float4*)cp;
        float ov[4];
#pragma unroll
        for (int j = 0; j < 4; j++) {
            float v = acc[i][j] + bi;
            if (EPI == 1) { v = g * (v - mu) * iv + bt; v = fmaxf(v, 0.f); }
            ov[j] = v;
        }
        if (EPI == 2) { ov[0] += old.x; ov[1] += old.y; ov[2] += old.z; ov[3] += old.w; }
        float4 o = make_float4(ov[0], ov[1], ov[2], ov[3]);
        *(float4*)cp = o;
    }
}

// ------------- attention score: att[bh][n][m] = Qh^T Kh / 8
//               128x128 tile, 256 threads, 8x8/thread QUADRANT layout (conflict-free) -------------
__global__ void __launch_bounds__(256) attn_score_k() {
    int bh = blockIdx.z, b = bh >> 2, h = bh & 3;
    const float* qh = g_qkv + (size_t)b * 3 * FEAT * KV + (size_t)h * KV;
    const float* kh = qh + (size_t)FEAT * KV;
    float* ah = g_att + (size_t)bh * KV * KV;
    int n0 = blockIdx.y * 128, m0 = blockIdx.x * 128;
    __shared__ float Qs[2][16][132];
    __shared__ float Ks[2][16][132];
    int tid = threadIdx.x, tx = tid & 15, ty = tid >> 4;
    int nn = tid & 127, kr = tid >> 7;
    const float* Qp = qh + n0 + nn;
    const float* Kp = kh + m0 + nn;

    float ra[8], rb[8];
#pragma unroll
    for (int p = 0; p < 8; p++) {
        int k = kr + p * 2;
        Qs[0][k][nn] = Qp[(size_t)k * 4 * KV];
        Ks[0][k][nn] = Kp[(size_t)k * 4 * KV];
    }
    __syncthreads();
    float acc[8][8] = {};
#pragma unroll
    for (int t = 0; t < 4; t++) {
        if (t < 3) {
#pragma unroll
            for (int p = 0; p < 8; p++) {
                int k = ((t + 1) << 4) + kr + p * 2;
                ra[p] = Qp[(size_t)k * 4 * KV];
                rb[p] = Kp[(size_t)k * 4 * KV];
            }
        }
        int cur = t & 1;
#pragma unroll
        for (int kk = 0; kk < 16; kk++) {
            float4 a0 = *(const float4*)&Qs[cur][kk][ty * 4];
            float4 a1 = *(const float4*)&Qs[cur][kk][64 + ty * 4];
            float4 b0 = *(const float4*)&Ks[cur][kk][tx * 4];
            float4 b1 = *(const float4*)&Ks[cur][kk][64 + tx * 4];
            float av[8] = {a0.x, a0.y, a0.z, a0.w, a1.x, a1.y, a1.z, a1.w};
            float bv[8] = {b0.x, b0.y, b0.z, b0.w, b1.x, b1.y, b1.z, b1.w};
#pragma unroll
            for (int i = 0; i < 8; i++)
#pragma unroll
                for (int j = 0; j < 8; j++) acc[i][j] += av[i] * bv[j];
        }
        if (t < 3) {
            int nxt = cur ^ 1;
#pragma unroll
            for (int p = 0; p < 8; p++) {
                Qs[nxt][kr + p * 2][nn] = ra[p];
                Ks[nxt][kr + p * 2][nn] = rb[p];
            }
        }
        __syncthreads();
    }
#pragma unroll
    for (int i = 0; i < 8; i++) {
        int n = n0 + ((i < 4) ? (ty * 4 + i) : (64 + ty * 4 + i - 4));
        float* op = &ah[(size_t)n * KV + m0];
        float4 o0 = make_float4(acc[i][0] * 0.125f, acc[i][1] * 0.125f,
                                acc[i][2] * 0.125f, acc[i][3] * 0.125f);
        float4 o1 = make_float4(acc[i][4] * 0.125f, acc[i][5] * 0.125f,
                                acc[i][6] * 0.125f, acc[i][7] * 0.125f);
        *(float4*)(op + tx * 4) = o0;
        *(float4*)(op + 64 + tx * 4) = o1;
    }
}

// ------------------------- mask + softmax over rows of g_att (R11) -------------------------
__global__ void softmax_k() {
    int bh = blockIdx.y, b = bh >> 2, n = blockIdx.x;
    float* row = g_att + (size_t)bh * KV * KV + (size_t)n * KV;
    const float* mk = g_mask + b * KV;
    int tid = threadIdx.x;
    float mrow = mk[n];
    float x[4]; float mx = -1e30f;
#pragma unroll
    for (int i = 0; i < 4; i++) {
        int m = tid + (i << 8);
        float v = row[m];
        if (mrow * mk[m] == 0.f) v = -1e9f;
        x[i] = v; mx = fmaxf(mx, v);
    }
    __shared__ float red[8];
    for (int o = 16; o; o >>= 1) mx = fmaxf(mx, __shfl_xor_sync(0xffffffffu, mx, o));
    if ((tid & 31) == 0) red[tid >> 5] = mx;
    __syncthreads();
    float bm = red[0];
#pragma unroll
    for (int w = 1; w < 8; w++) bm = fmaxf(bm, red[w]);
    __syncthreads();
    float s = 0.f;
#pragma unroll
    for (int i = 0; i < 4; i++) { x[i] = __expf(x[i] - bm); s += x[i]; }
    for (int o = 16; o; o >>= 1) s += __shfl_xor_sync(0xffffffffu, s, o);
    if ((tid & 31) == 0) red[tid >> 5] = s;
    __syncthreads();
    float bs = 0.f;
#pragma unroll
    for (int w = 0; w < 8; w++) bs += red[w];
    float inv = 1.f / bs;
#pragma unroll
    for (int i = 0; i < 4; i++) row[tid + (i << 8)] = x[i] * inv;
}

// ------- attention apply, K-SPLIT x4 (R15 proven) -------
__global__ void __launch_bounds__(256) attn_apply_k() {
    int bh = blockIdx.z, b = bh >> 2, h = bh & 3;
    int kc = blockIdx.y;
    const float* ph = g_att + (size_t)bh * KV * KV;
    const float* vh = g_qkv + (size_t)b * 3 * FEAT * KV + (size_t)2 * FEAT * KV
                    + (size_t)h * KV;
    float* outp = g_msgp[kc] + (size_t)b * FEAT * KV;
    int n0 = blockIdx.x * 64;
    int mbase = kc * 256;
    __shared__ float As[2][16][68];
    __shared__ float Bs[2][16][68];
    int tid = threadIdx.x, tx = tid & 15, ty = tid >> 4;
    int ac = tid & 15, ar = tid >> 4;
    int bc = tid & 15, br = tid >> 4;

    float ra[4], rb[4];
#pragma unroll
    for (int p = 0; p < 4; p++) {
        int d = ar + p * 16;
        As[0][ac][d] = vh[(size_t)(d * 4) * KV + mbase + ac];
        int n = br + p * 16;
        Bs[0][bc][n] = ph[(size_t)(n0 + n) * KV + mbase + bc];
    }
    __syncthreads();
    float acc[4][4] = {};
    for (int t = 0; t < 16; t++) {
        int m0n = mbase + ((t + 1) << 4);
        if (t < 15) {
#pragma unroll
            for (int p = 0; p < 4; p++) {
                int d = ar + p * 16;
                ra[p] = vh[(size_t)(d * 4) * KV + m0n + ac];
                int n = br + p * 16;
                rb[p] = ph[(size_t)(n0 + n) * KV + m0n + bc];
            }
        }
        int cur = t & 1;
#pragma unroll
        for (int kk = 0; kk < 16; kk++) {
            float4 a0 = *(const float4*)&As[cur][kk][ty * 4];
            float4 b0 = *(const float4*)&Bs[cur][kk][tx * 4];
            float av[4] = {a0.x, a0.y, a0.z, a0.w};
            float bv[4] = {b0.x, b0.y, b0.z, b0.w};
#pragma unroll
            for (int i = 0; i < 4; i++)
#pragma unroll
                for (int j = 0; j < 4; j++) acc[i][j] += av[i] * bv[j];
        }
        if (t < 15) {
            int nxt = cur ^ 1;
#pragma unroll
            for (int p = 0; p < 4; p++) {
                As[nxt][ac][ar + p * 16] = ra[p];
                Bs[nxt][bc][br + p * 16] = rb[p];
            }
        }
        __syncthreads();
    }
#pragma unroll
    for (int i = 0; i < 4; i++) {
        int d = ty * 4 + i;
        float4 o = make_float4(acc[i][0], acc[i][1], acc[i][2], acc[i][3]);
        *(float4*)&outp[(size_t)(d * 4 + h) * KV + n0 + tx * 4] = o;
    }
}

// ------------------------- reduce 4 k-split partials into g_msg -------------------------
__global__ void msg_reduce_k() {
    const size_t N = (size_t)NB * FEAT * KV / 4;
    size_t i = (size_t)blockIdx.x * 256 + threadIdx.x;
    if (i >= N) return;
    const float4* p0 = reinterpret_cast<const float4*>(g_msgp[0]);
    const float4* p1 = reinterpret_cast<const float4*>(g_msgp[1]);
    const float4* p2 = reinterpret_cast<const float4*>(g_msgp[2]);
    const float4* p3 = reinterpret_cast<const float4*>(g_msgp[3]);
    float4 a = p0[i], b = p1[i], c = p2[i], d = p3[i];
    float4 o = make_float4(a.x + b.x + c.x + d.x, a.y + b.y + c.y + d.y,
                           a.z + b.z + c.z + d.z, a.w + b.w + c.w + d.w);
    reinterpret_cast<float4*>(g_msg)[i] = o;
}

// ------------------------- Gram: coup[n][m] = md^T md / 16
//               128x128 tile, 256 threads, 8x8/thread QUADRANT layout -------------------------
__global__ void __launch_bounds__(256) gram_k() {
    int b = blockIdx.z;
    const float* mb = g_md + (size_t)b * FEAT * KV;
    float* cb = g_coup + (size_t)b * CPLSZ;
    int n0 = blockIdx.y * 128, m0 = blockIdx.x * 128;
    __shared__ float Ns[2][16][132];
    __shared__ float Ms[2][16][132];
    int tid = threadIdx.x, tx = tid & 15, ty = tid >> 4;
    int nn = tid & 127, kr = tid >> 7;
    const float* Np = mb + n0 + nn;
    const float* Mp = mb + m0 + nn;

    float ra[8], rb[8];
#pragma unroll
    for (int p = 0; p < 8; p++) {
        int k = kr + p * 2;
        Ns[0][k][nn] = Np[(size_t)k * KV];
        Ms[0][k][nn] = Mp[(size_t)k * KV];
    }
    __syncthreads();
    float acc[8][8] = {};
    for (int t = 0; t < 16; t++) {
        if (t < 15) {
            int k0n = (t + 1) << 4;
#pragma unroll
            for (int p = 0; p < 8; p++) {
                int k = k0n + kr + p * 2;
                ra[p] = Np[(size_t)k * KV];
                rb[p] = Mp[(size_t)k * KV];
            }
        }
        int cur = t & 1;
#pragma unroll
        for (int kk = 0; kk < 16; kk++) {
            float4 a0 = *(const float4*)&Ns[cur][kk][ty * 4];
            float4 a1 = *(const float4*)&Ns[cur][kk][64 + ty * 4];
            float4 b0 = *(const float4*)&Ms[cur][kk][tx * 4];
            float4 b1 = *(const float4*)&Ms[cur][kk][64 + tx * 4];
            float av[8] = {a0.x, a0.y, a0.z, a0.w, a1.x, a1.y, a1.z, a1.w};
            float bv[8] = {b0.x, b0.y, b0.z, b0.w, b1.x, b1.y, b1.z, b1.w};
#pragma unroll
            for (int i = 0; i < 8; i++)
#pragma unroll
                for (int j = 0; j < 8; j++) acc[i][j] += av[i] * bv[j];
        }
        if (t < 15) {
            int nxt = cur ^ 1;
#pragma unroll
            for (int p = 0; p < 8; p++) {
                Ns[nxt][kr + p * 2][nn] = ra[p];
                Ms[nxt][kr + p * 2][nn] = rb[p];
            }
        }
        __syncthreads();
    }
    const float sc = 1.f / 16.f;
#pragma unroll
    for (int i = 0; i < 8; i++) {
        int n = n0 + ((i < 4) ? (ty * 4 + i) : (64 + ty * 4 + i - 4));
        float* op = &cb[(size_t)n * CPL + m0];
#pragma unroll
        for (int j = 0; j < 4; j++) op[tx * 4 + j] = acc[i][j] * sc;
#pragma unroll
        for (int j = 4; j < 8; j++) op[64 + tx * 4 + j - 4] = acc[i][j] * sc;
    }
}

__global__ void border_k(const float* __restrict__ alpha) {
    float a = alpha[0];
    int b = blockIdx.y;
    int i = blockIdx.x * 256 + threadIdx.x;
    float* cb = g_coup + (size_t)b * CPLSZ;
    if (i < CPL) {
        cb[(size_t)i * CPL + 1024] = a;
        cb[(size_t)1024 * CPL + i] = a;
    }
}

// ------------------------- Sinkhorn precompute (fp32) -------------------------
__global__ void rowmax_k() {
    int b = blockIdx.y;
    int n = blockIdx.x * 8 + (threadIdx.x >> 5);
    int lane = threadIdx.x & 31;
    if (n >= CPL) return;
    const float* row = g_coup + (size_t)b * CPLSZ + (size_t)n * CPL;
    float m = -1e30f;
    for (int j = lane; j < CPL; j += 32) m = fmaxf(m, row[j]);
    for (int o = 16; o; o >>= 1) m = fmaxf(m, __shfl_xor_sync(0xffffffffu, m, o));
    if (!lane) g_rmax[b * CPL + n] = m;
}

__global__ void colmax_k() {
    int b = blockIdx.y;
    int lane = threadIdx.x & 31, r = threadIdx.x >> 5;
    int col = blockIdx.x * 32 + lane;
    const float* cp = g_coup + (size_t)b * CPLSZ;
    float m = -1e30f;
    if (col < CPL)
        for (int n = r; n < CPL; n += 8) m = fmaxf(m, cp[(size_t)n * CPL + col]);
    __shared__ float sm[8][33];
    sm[r][lane] = m;
    __syncthreads();
    if (r == 0 && col < CPL) {
        float M = sm[0][lane];
        for (int w = 1; w < 8; w++) M = fmaxf(M, sm[w][lane]);
        g_cmax[b * CPL + col] = M;
    }
}

__global__ void build_exp_k() {
    int b = blockIdx.z;
    int j0 = blockIdx.x * 32, n0 = blockIdx.y * 32;
    const float* cp = g_coup + (size_t)b * CPLSZ;
    __shared__ float t[32][33];
    int tx = threadIdx.x;
    for (int r = threadIdx.y; r < 32; r += 8) {
        int n = n0 + r, j = j0 + tx;
        float c = (n < CPL && j < CPL) ? cp[(size_t)n * CPL + j] : -1e30f;
        if (n < CPL && j < CSTR) {
            float rm = g_rmax[b * CPL + n];
            g_Er[((size_t)b * CPL + n) * CSTR + j] = (j < CPL) ? __expf(c - rm) : 0.f;
        }
        float cm = (j < CPL) ? g_cmax[b * CPL + j] : 0.f;
        t[tx][r] = (n < CPL && j < CPL) ? __expf(c - cm) : 0.f;
    }
    __syncthreads();
    for (int r = threadIdx.y; r < 32; r += 8) {
        int j = j0 + r, n = n0 + tx;
        if (j < CPL && n < CSTR)
            g_EcT[((size_t)b * CPL + j) * CSTR + n] = t[r][tx];
    }
}

__global__ void init_w_k() {
    int i = blockIdx.x * 256 + threadIdx.x;
    if (i < NB * CSTR) {
        int j = i % CSTR;
        g_w[i]  = (j < CPL) ? 1.f : 0.f;
        g_wu[i] = 0.f;
    }
}

// ------------------------- Sinkhorn GEMV passes (fp32, multi-launch) -------------------------
__global__ void sink_row_f() {
    int b = blockIdx.y;
    int n = blockIdx.x * 8 + (threadIdx.x >> 5);
    int lane = threadIdx.x & 31;
    if (n >= CPL) return;
    const float4* row = reinterpret_cast<const float4*>(g_Er + ((size_t)b * CPL + n) * CSTR);
    const float4* w4  = reinterpret_cast<const float4*>(g_w + b * CSTR);
    float dot = 0.f;
#pragma unroll 4
    for (int i = lane; i < CSTR / 4; i += 32) {
        float4 e = row[i], ww = w4[i];
        dot += e.x * ww.x; dot += e.y * ww.y; dot += e.z * ww.z; dot += e.w * ww.w;
    }
    for (int o = 16; o; o >>= 1) dot += __shfl_xor_sync(0xffffffffu, dot, o);
    if (!lane) {
        float lmu = (n < 1024) ? NORM_C : LOGLAST;
        float u = lmu - g_rmax[b * CPL + n] - logf(dot);
        g_u[b * CPL + n] = u;
        g_wu[b * CSTR + n] = expf(u);
    }
}

__global__ void sink_col_f() {
    int b = blockIdx.y;
    int j = blockIdx.x * 8 + (threadIdx.x >> 5);
    int lane = threadIdx.x & 31;
    if (j >= CPL) return;
    const float4* row = reinterpret_cast<const float4*>(g_EcT + ((size_t)b * CPL + j) * CSTR);
    const float4* w4  = reinterpret_cast<const float4*>(g_wu + b * CSTR);
    float dot = 0.f;
#pragma unroll 4
    for (int i = lane; i < CSTR / 4; i += 32) {
        float4 e = row[i], ww = w4[i];
        dot += e.x * ww.x; dot += e.y * ww.y; dot += e.z * ww.z; dot += e.w * ww.w;
    }
    for (int o = 16; o; o >>= 1) dot += __shfl_xor_sync(0xffffffffu, dot, o);
    if (!lane) {
        float lnu = (j < 1024) ? NORM_C : LOGLAST;
        float v = lnu - g_cmax[b * CPL + j] - logf(dot);
        g_vv[b * CPL + j] = v;
        g_w[b * CSTR + j] = expf(v);
    }
}

__global__ void out_k(float* __restrict__ out) {
    int b = blockIdx.y, n = blockIdx.x;
    const float* cb = g_coup + (size_t)b * CPLSZ + (size_t)n * CPL;
    float un = g_u[b * CPL + n];
    const float* v = g_vv + b * CPL;
    float* ob = out + (size_t)b * CPLSZ + (size_t)n * CPL;
    for (int j = threadIdx.x; j < CPL; j += 256)
        ob[j] = cb[j] + un + v[j] - NORM_C;
}

// ------------------------- host -------------------------
static inline void gemm(const float* A, const float* B, float* C, const float* bias,
                        int M, int K, long sB, long sC, int epi, const float* bn) {
    dim3 g(16, M / 64, NB);
    if (epi == 0)      gemm_k<0><<<g, 256>>>(A, B, C, bias, bn, M, K, sB, sC);
    else if (epi == 1) gemm_k<1><<<g, 256>>>(A, B, C, bias, bn, M, K, sB, sC);
    else               gemm_k<2><<<g, 256>>>(A, B, C, bias, bn, M, K, sB, sC);
}

extern "C" void kernel_launch(void* const* d_in, const int* in_sizes, int n_in,
                              void* d_out, int out_size) {
    const float* scores   = (const float*)d_in[0];
    const float* distance = (const float*)d_in[1];
    const float* enc_W0   = (const float*)d_in[2];
    const float* enc_b0   = (const float*)d_in[3];
    const float* enc_bn   = (const float*)d_in[4];
    const float* enc_W1   = (const float*)d_in[5];
    const float* enc_b1   = (const float*)d_in[6];
    const float* gnn_Wqkv = (const float*)d_in[7];
    const float* gnn_bqkv = (const float*)d_in[8];
    const float* gnn_Wm   = (const float*)d_in[9];
    const float* gnn_bm   = (const float*)d_in[10];
    const float* gnn_W1   = (const float*)d_in[11];
    const float* gnn_b1   = (const float*)d_in[12];
    const float* gnn_bn   = (const float*)d_in[13];
    const float* gnn_W2   = (const float*)d_in[14];
    const float* gnn_b2   = (const float*)d_in[15];
    const float* final_W  = (const float*)d_in[16];
    const float* final_b  = (const float*)d_in[17];
    const float* alpha    = (const float*)d_in[18];
    float* out = (float*)d_out;

    static bool attr_done = false;
    if (!attr_done) {
        cudaFuncSetAttribute(nms_kernel,  cudaFuncAttributeMaxDynamicSharedMemorySize, 5 * NCELL * 4);
        cudaFuncSetAttribute(topk_kernel, cudaFuncAttributeMaxDynamicSharedMemorySize, NPAD * 8);
        attr_done = true;
    }

    float *devEmb=nullptr, *devQKV=nullptr, *devMsg=nullptr, *devCat=nullptr,
          *devY=nullptr, *devMd=nullptr;
    cudaGetSymbolAddress((void**)&devEmb, g_embT);
    cudaGetSymbolAddress((void**)&devQKV, g_qkv);
    cudaGetSymbolAddress((void**)&devMsg, g_msg);
    cudaGetSymbolAddress((void**)&devCat, g_cat);
    cudaGetSymbolAddress((void**)&devY,   g_y);
    cudaGetSymbolAddress((void**)&devMd,  g_md);

    const long sF  = (long)FEAT * KV;       // 262144
    const long s2F = 2L * FEAT * KV;        // 524288
    const long s3F = 3L * FEAT * KV;        // 786432
    const long sE  = (long)DIN * KV;

    // 1. NMS + top-k + embedding
    nms_kernel<<<NB, 256, 5 * NCELL * 4>>>(scores);
    topk_kernel<<<NB, 256, NPAD * 8>>>();
    emb_kernel<<<dim3(KV, NB), 256>>>(distance);

    // 2. encoder
    gemm(enc_W0, devEmb, devY, enc_b0, FEAT, DIN, sE, sF, 1, enc_bn);
    gemm(enc_W1, devY, devCat, enc_b1, FEAT, FEAT, sF, s2F, 0, nullptr);

    // 3. GNN layers
    for (int l = 0; l < 4; l++) {
        gemm(gnn_Wqkv + (size_t)l * 3 * FEAT * FEAT, devCat, devQKV,
             gnn_bqkv + l * 3 * FEAT, 3 * FEAT, FEAT, s2F, s3F, 0, nullptr);

        attn_score_k<<<dim3(8, 8, NB * 4), 256>>>();
        softmax_k<<<dim3(KV, NB * 4), 256>>>();
        attn_apply_k<<<dim3(16, 4, NB * 4), 256>>>();
        msg_reduce_k<<<4096, 256>>>();

        gemm(gnn_Wm + (size_t)l * FEAT * FEAT, devMsg, devCat + (size_t)FEAT * KV,
             gnn_bm + l * FEAT, FEAT, FEAT, sF, s2F, 0, nullptr);
        gemm(gnn_W1 + (size_t)l * 512 * 512, devCat, devY,
             gnn_b1 + l * 512, 512, 512, s2F, s2F, 1, gnn_bn + (size_t)l * 4 * 512);
        gemm(gnn_W2 + (size_t)l * FEAT * 512, devY, devCat,
             gnn_b2 + l * FEAT, FEAT, 512, s2F, s2F, 2, nullptr);
    }

    // 4. final descriptors + Gram + couplings
    gemm(final_W, devCat, devMd, final_b, FEAT, FEAT, s2F, sF, 0, nullptr);
    gram_k<<<dim3(8, 8, NB), 256>>>();
    border_k<<<dim3(5, NB), 256>>>(alpha);

    // 5. Sinkhorn: factorized fp32 exp-matrices -> GEMV passes
    rowmax_k<<<dim3(129, NB), 256>>>();
    colmax_k<<<dim3(33, NB), 256>>>();
    build_exp_k<<<dim3(33, 33, NB), dim3(32, 8)>>>();
    init_w_k<<<17, 256>>>();
    for (int it = 0; it < 100; it++) {
        sink_row_f<<<dim3(129, NB), 256>>>();
        sink_col_f<<<dim3(129, NB), 256>>>();
    }

    // 6. output
    out_k<<<dim3(CPL, NB), 256>>>(out);
}